// round 16
// baseline (speedup 1.0000x reference)
#include <cuda_runtime.h>
#include <math.h>

#define SPB       64
#define T_LEN     34
#define NTOK      (SPB * T_LEN)   // 2176
#define BT        128
#define CSTRIDE   35
#define USTRIDE   35
#define WSTRIDE   36

__constant__ int c_flat[T_LEN] = {
    0,1,2,3,4,5,6,7,8,9, 11,
    0,1,2,3,4,5,6,7,8,9, 12,
    0,1,2,3,4,5,6,7,8,9, 10, 13
};

__device__ __forceinline__ float ex2f(float x) {
    float y;
    asm("ex2.approx.ftz.f32 %0, %1;" : "=f"(y) : "f"(x));
    return y;
}
__device__ __forceinline__ float rcpf(float x) {
    float y;
    asm("rcp.approx.ftz.f32 %0, %1;" : "=f"(y) : "f"(x));
    return y;
}
__device__ __forceinline__ float gelu_fast(float z) {
    float a  = z * 0.70710678118654752f;
    float ax = fabsf(a);
    float t  = rcpf(fmaf(0.3275911f, ax, 1.0f));
    float p  = t * fmaf(t, fmaf(t, fmaf(t, fmaf(t, 1.061405429f, -1.453152027f),
                                        1.421413741f), -0.284496736f), 0.254829592f);
    float em = ex2f(-1.4426950408889634f * a * a);
    float er = fmaf(-p, em, 1.0f);
    er = copysignf(er, a);
    return 0.5f * z * (1.0f + er);
}

// triangular matvec for t in [T0,T1): dA[t] = sum_{s<=t} F[t][s]*v[s]
template<int T0, int T1>
__device__ __forceinline__ void matvec_seq(
    const unsigned char* __restrict__ crow,
    const float* __restrict__ sW,
    const float4* __restrict__ sxc,
    float* __restrict__ du)          // s_u0 + y*USTRIDE; scalar, conflict-free
{
    float v[T1];
    #pragma unroll
    for (int s = 0; s < T1; ++s) v[s] = sxc[(int)crow[s]].z;

    #pragma unroll
    for (int t = T0; t < T1; ++t) {
        const float* __restrict__ w = sW + t * WSTRIDE;
        float a0 = 0.f, a1 = 0.f;
        const int nf = ((t + 1) >> 2) << 2;
        #pragma unroll
        for (int s = 0; s < nf; s += 4) {
            float4 w4 = *(const float4*)(w + s);
            a0 = fmaf(w4.x, v[s],   a0);
            a1 = fmaf(w4.y, v[s+1], a1);
            a0 = fmaf(w4.z, v[s+2], a0);
            a1 = fmaf(w4.w, v[s+3], a1);
        }
        #pragma unroll
        for (int s = nf; s <= t; ++s) a0 = fmaf(w[s], v[s], a0);
        du[t] = a0 + a1;
    }
}

__global__ __launch_bounds__(BT, 8)
void micro_fused16(
    const int*   __restrict__ idx,
    const float* __restrict__ tokA,
    const float* __restrict__ tokStart,
    const float* __restrict__ tokStride,
    const float* __restrict__ z_hi,
    const float* __restrict__ specialEq,
    const float* __restrict__ qW,         // (4,3)
    const float* __restrict__ phase,
    const float* __restrict__ outA,       // (5,)
    const float* __restrict__ outB,       // (5,)
    const float* __restrict__ nw,         // (5,)
    const float* __restrict__ fc1,        // (2,5)
    const float* __restrict__ hp,         // (2,5)
    float*       __restrict__ out,        // (B,34,10)
    int B)
{
    __shared__ float  s_W [T_LEN * WSTRIDE];       // E -> folded F (4.9 KB)
    __shared__ unsigned char s_c[SPB * CSTRIDE];   // digits (2.2 KB)
    __shared__ __align__(16) float s_u0[SPB * USTRIDE];  // dA -> u0 (9 KB), stride 35: conflict-free
    __shared__ __align__(16) float s_u1[SPB * USTRIDE];  // u1 (9 KB)
    __shared__ float4 s_xc[10];                    // (x0,x1,Vt,0)
    __shared__ float2 s_tt[10];                    // (x0,x1) tok table
    __shared__ float4 s_xp[T_LEN];                 // (p0,p1,p2,0)
    __shared__ float  s_r [T_LEN];
    __shared__ float  s_dinv[T_LEN];
    __shared__ float  s_sc[40];                    // cB[0..4], hp[5..14], wf[15..24], wh[25..34]

    // build-time overlays on s_u0 (dead until matvec writes)
    float4* s_mt = reinterpret_cast<float4*>(s_u0);          // [34]
    float4* s_pt = reinterpret_cast<float4*>(s_u0) + T_LEN;  // [34]

    const int  tid       = threadIdx.x;
    const long base_tok  = (long)blockIdx.x * NTOK;
    const long total_tok = (long)B * T_LEN;

    // ---- P1: idx -> digits; parameter tables ----
    #pragma unroll
    for (int r = 0; r < 17; ++r) {
        int li = tid + r * BT;                   // 0..2175
        int  yy = li / T_LEN;
        int  ss = li - yy * T_LEN;
        long g  = base_tok + li;
        int  v  = (g < total_tok) ? idx[g] : 0;
        s_c[yy * CSTRIDE + ss] = (unsigned char)v;
    }
    if (tid < 40) {                              // scalar params: all 35 entries covered
        int i = tid;
        float v = 0.f;
        if (i < 5)       v = outB[i];
        else if (i < 15) v = hp[i - 5];
        else if (i < 25) v = nw[(i - 15) % 5] * fc1[i - 15];
        else if (i < 35) v = nw[(i - 25) % 5] * hp[i - 25];
        s_sc[i] = v;
    }
    if (tid >= 64 && tid < 64 + T_LEN) {         // warps 2-3: positions
        const int t = tid - 64;
        const int f = c_flat[t];
        float p0, p1, p2;
        if (f < 10) {
            float a = 0.6283185307179586f * (float)f;
            p0 = 3.5f * __cosf(a);
            p1 = 3.5f * __sinf(a);
            p2 = 0.15f * (float)f;
        } else if (f == 10) {
            p0 = z_hi[0]; p1 = z_hi[1]; p2 = z_hi[2];
        } else if (f == 12) {
            p0 = specialEq[0]; p1 = specialEq[1]; p2 = specialEq[2];
        } else {
            p0 = p1 = p2 = 0.0f;
        }
        float pp = p0*p0 + p1*p1 + p2*p2;
        s_xp[t] = make_float4(p0, p1, p2, 0.f);

        float amp = tokA[0];
        s_r[t] = rsqrtf(fmaf(0.2f, fmaf(amp, amp, pp), 1e-5f));

        float pt0 = p0 * nw[2], pt1 = p1 * nw[3], pt2 = p2 * nw[4];
        s_pt[t] = make_float4(pt0, pt1, pt2, 0.f);

        float q0 = qW[0]*pt0 + qW[1]*pt1 + qW[2]*pt2;
        float q1 = qW[3]*pt0 + qW[4]*pt1 + qW[5]*pt2;
        float q2 = qW[6]*pt0 + qW[7]*pt1 + qW[8]*pt2;
        float q3 = qW[9]*pt0 + qW[10]*pt1 + qW[11]*pt2;
        float cp = __cosf(phase[0]);
        float sp = __sinf(phase[0]);
        float r0  = q0*cp - q1*sp;
        float r1v = q0*sp + q1*cp;
        float r2v = q2*cp - q3*sp;
        float r3  = q2*sp + q3*cp;
        const float LG = 0.5f * 1.4426950408889634f;
        s_mt[t] = make_float4(
            LG*(r0*qW[0] + r1v*qW[3] + r2v*qW[6] + r3*qW[9]),
            LG*(r0*qW[1] + r1v*qW[4] + r2v*qW[7] + r3*qW[10]),
            LG*(r0*qW[2] + r1v*qW[5] + r2v*qW[8] + r3*qW[11]), 0.f);
    }
    if (tid >= 48 && tid < 58) {                 // warp 1: digit table
        const int c = tid - 48;
        float ang = tokStart[0] + (float)c * tokStride[0];
        float amp = tokA[0];
        float x0 = amp * __cosf(ang);
        float x1 = amp * __sinf(ang);
        float w0s = hp[0]*outA[0] + hp[1]*outA[1] + hp[2]*outA[2] + hp[3]*outA[3] + hp[4]*outA[4];
        float w1s = hp[5]*outA[0] + hp[6]*outA[1] + hp[7]*outA[2] + hp[8]*outA[3] + hp[9]*outA[4];
        float vt  = x0 * nw[0] * w0s + x1 * nw[1] * w1s;
        s_xc[c] = make_float4(x0, x1, vt, 0.f);
        s_tt[c] = make_float2(x0, x1);
    }
    __syncthreads();

    // ---- P2: E[t][s] = exp2(r_t r_s g(t,s)) ----
    #pragma unroll 1
    for (int li = tid; li < T_LEN * T_LEN; li += BT) {
        int t = li / T_LEN;
        int s = li - t * T_LEN;
        if (s <= t) {
            float4 m = s_mt[t];
            float4 p = s_pt[s];
            float g  = fmaf(m.x, p.x, fmaf(m.y, p.y, m.z * p.z));
            s_W[t * WSTRIDE + s] = ex2f((s_r[t] * s_r[s]) * g);
        }
    }
    __syncthreads();

    // ---- P3a: row denominators ----
    if (tid < T_LEN) {
        const float* wr = s_W + tid * WSTRIDE;
        float d0 = 0.f, d1 = 0.f;
        const int nf = ((tid + 1) >> 2) << 2;
        for (int s = 0; s < nf; s += 4) {
            float4 w4 = *(const float4*)(wr + s);
            d0 += w4.x + w4.z;
            d1 += w4.y + w4.w;
        }
        for (int s = nf; s <= tid; ++s) d0 += wr[s];
        s_dinv[tid] = rcpf(d0 + d1);
    }
    __syncthreads();

    // ---- P3b: fold F = E * dinv[t] * r[s] ----
    #pragma unroll 1
    for (int li = tid; li < T_LEN * T_LEN; li += BT) {
        int t = li / T_LEN;
        int s = li - t * T_LEN;
        if (s <= t) s_W[t * WSTRIDE + s] *= s_dinv[t] * s_r[s];
    }
    __syncthreads();

    // ---- P4: triangular matvec, thread-per-sequence, dA -> s_u0 ----
    {
        const int role = tid >> 6;
        const int y    = tid & 63;
        const unsigned char* __restrict__ crow = s_c + y * CSTRIDE;
        float* __restrict__ du = s_u0 + y * USTRIDE;
        if (role == 0) matvec_seq<0, 24>(crow, s_W, s_xc, du);
        else           matvec_seq<24, T_LEN>(crow, s_W, s_xc, du);
    }
    __syncthreads();

    const float* s_cB = s_sc;
    const float* s_hp = s_sc + 5;
    const float* s_wf = s_sc + 15;
    const float* s_wh = s_sc + 25;

    // ---- P5: epilogue per token, in-place: dA -> (u0,u1) (conflict-free) ----
    #pragma unroll 1
    for (int r = 0; r < 17; ++r) {
        int it = tid + r * BT;                   // 0..2175
        const int t = it >> 6;                   // warp-uniform
        const int y = it & 63;
        const int ui = y * USTRIDE + t;
        const float dA = s_u0[ui];
        const int c = (int)s_c[y * CSTRIDE + t];

        const float4 xc = s_xc[c];
        const float4 xp = s_xp[t];
        float X0 = fmaf(dA, s_cB[0], xc.x);
        float X1 = fmaf(dA, s_cB[1], xc.y);
        float X2 = fmaf(dA, s_cB[2], xp.x);
        float X3 = fmaf(dA, s_cB[3], xp.y);
        float X4 = fmaf(dA, s_cB[4], xp.z);

        float ss1 = fmaf(X0,X0, fmaf(X1,X1, fmaf(X2,X2, fmaf(X3,X3, X4*X4))));
        float r1  = rsqrtf(fmaf(0.2f, ss1, 1e-5f));
        float z0 = r1 * (X0*s_wf[0] + X1*s_wf[1] + X2*s_wf[2] + X3*s_wf[3] + X4*s_wf[4]);
        float z1 = r1 * (X0*s_wf[5] + X1*s_wf[6] + X2*s_wf[7] + X3*s_wf[8] + X4*s_wf[9]);
        float g0 = gelu_fast(z0);
        float g1 = gelu_fast(z1);
        float Y0 = X0 + g0*s_hp[0] + g1*s_hp[5];
        float Y1 = X1 + g0*s_hp[1] + g1*s_hp[6];
        float Y2 = X2 + g0*s_hp[2] + g1*s_hp[7];
        float Y3 = X3 + g0*s_hp[3] + g1*s_hp[8];
        float Y4 = X4 + g0*s_hp[4] + g1*s_hp[9];

        float ss2 = fmaf(Y0,Y0, fmaf(Y1,Y1, fmaf(Y2,Y2, fmaf(Y3,Y3, Y4*Y4))));
        float r2  = rsqrtf(fmaf(0.2f, ss2, 1e-5f));
        float u0 = r2 * (Y0*s_wh[0] + Y1*s_wh[1] + Y2*s_wh[2] + Y3*s_wh[3] + Y4*s_wh[4]);
        float u1 = r2 * (Y0*s_wh[5] + Y1*s_wh[6] + Y2*s_wh[7] + Y3*s_wh[8] + Y4*s_wh[9]);

        s_u0[ui] = u0;
        s_u1[ui] = u1;
    }
    __syncthreads();

    // ---- P6: output, 2 tokens (20 floats = 5 float4) per chunk, static d-pattern ----
    {
        float tt0[10], tt1[10];
        #pragma unroll
        for (int d = 0; d < 10; ++d) { float2 w = s_tt[d]; tt0[d] = w.x; tt1[d] = w.y; }

        const long base_f  = base_tok * 10;
        const long total_f = total_tok * 10;
        float* __restrict__ ob = out + base_f;
        const int nch = NTOK / 2;                // 1088

        #pragma unroll 1
        for (int q = tid; q < nch; q += BT) {
            const int el = q * 20;
            const int tok0 = q * 2;
            int y0 = tok0 / T_LEN;
            int t0 = tok0 - y0 * T_LEN;
            int y1 = y0, t1 = t0 + 1;
            if (t1 == T_LEN) { t1 = 0; ++y1; }

            if (base_f + el + 20 <= total_f) {
                const float ua0 = s_u0[y0 * USTRIDE + t0];
                const float ua1 = s_u1[y0 * USTRIDE + t0];
                const float ub0 = s_u0[y1 * USTRIDE + t1];
                const float ub1 = s_u1[y1 * USTRIDE + t1];

                float4* __restrict__ op = reinterpret_cast<float4*>(ob + el);
                #pragma unroll
                for (int j = 0; j < 5; ++j) {
                    float v[4];
                    #pragma unroll
                    for (int k = 0; k < 4; ++k) {
                        const int e = 4 * j + k;
                        const int d = (e < 10) ? e : e - 10;
                        const float w0 = (e < 10) ? ua0 : ub0;
                        const float w1 = (e < 10) ? ua1 : ub1;
                        v[k] = fmaf(w1, tt1[d], w0 * tt0[d]);
                    }
                    op[j] = make_float4(v[0], v[1], v[2], v[3]);
                }
            }
        }
    }
}

extern "C" void kernel_launch(void* const* d_in, const int* in_sizes, int n_in,
                              void* d_out, int out_size)
{
    const int B = in_sizes[0] / T_LEN;
    const int grid = (B + SPB - 1) / SPB;
    micro_fused16<<<grid, BT>>>(
        (const int*)d_in[0],
        (const float*)d_in[1],
        (const float*)d_in[2],
        (const float*)d_in[3],
        (const float*)d_in[4],
        (const float*)d_in[5],
        (const float*)d_in[6],
        (const float*)d_in[7],
        (const float*)d_in[8],
        (const float*)d_in[9],
        (const float*)d_in[10],
        (const float*)d_in[11],
        (const float*)d_in[12],
        (float*)d_out, B);
}

// round 17
// speedup vs baseline: 1.6226x; 1.6226x over previous
#include <cuda_runtime.h>
#include <math.h>

#define SPB       64
#define T_LEN     34
#define NTOK      (SPB * T_LEN)   // 2176
#define BT        128
#define CSTRIDE   35
#define USTRIDE   35
#define WSTRIDE   36

__constant__ int c_flat[T_LEN] = {
    0,1,2,3,4,5,6,7,8,9, 11,
    0,1,2,3,4,5,6,7,8,9, 12,
    0,1,2,3,4,5,6,7,8,9, 10, 13
};

__device__ __forceinline__ float ex2f(float x) {
    float y;
    asm("ex2.approx.ftz.f32 %0, %1;" : "=f"(y) : "f"(x));
    return y;
}
__device__ __forceinline__ float rcpf(float x) {
    float y;
    asm("rcp.approx.ftz.f32 %0, %1;" : "=f"(y) : "f"(x));
    return y;
}
__device__ __forceinline__ float gelu_fast(float z) {
    float a  = z * 0.70710678118654752f;
    float ax = fabsf(a);
    float t  = rcpf(fmaf(0.3275911f, ax, 1.0f));
    float p  = t * fmaf(t, fmaf(t, fmaf(t, fmaf(t, 1.061405429f, -1.453152027f),
                                        1.421413741f), -0.284496736f), 0.254829592f);
    float em = ex2f(-1.4426950408889634f * a * a);
    float er = fmaf(-p, em, 1.0f);
    er = copysignf(er, a);
    return 0.5f * z * (1.0f + er);
}

// triangular matvec for t in [T0,T1): dA[t] = sum_{s<=t} F[t][s]*v[s]
template<int T0, int T1>
__device__ __forceinline__ void matvec_seq(
    const unsigned char* __restrict__ crow,
    const float* __restrict__ sW,
    const float4* __restrict__ sxc,
    float* __restrict__ du)          // s_u0 + y*USTRIDE; scalar, conflict-free
{
    float v[T1];
    #pragma unroll
    for (int s = 0; s < T1; ++s) v[s] = sxc[(int)crow[s]].z;

    #pragma unroll
    for (int t = T0; t < T1; ++t) {
        const float* __restrict__ w = sW + t * WSTRIDE;
        float a0 = 0.f, a1 = 0.f;
        const int nf = ((t + 1) >> 2) << 2;
        #pragma unroll
        for (int s = 0; s < nf; s += 4) {
            float4 w4 = *(const float4*)(w + s);
            a0 = fmaf(w4.x, v[s],   a0);
            a1 = fmaf(w4.y, v[s+1], a1);
            a0 = fmaf(w4.z, v[s+2], a0);
            a1 = fmaf(w4.w, v[s+3], a1);
        }
        #pragma unroll
        for (int s = nf; s <= t; ++s) a0 = fmaf(w[s], v[s], a0);
        du[t] = a0 + a1;
    }
}

__global__ __launch_bounds__(BT, 8)
void micro_fused17(
    const int*   __restrict__ idx,
    const float* __restrict__ tokA,
    const float* __restrict__ tokStart,
    const float* __restrict__ tokStride,
    const float* __restrict__ z_hi,
    const float* __restrict__ specialEq,
    const float* __restrict__ qW,         // (4,3)
    const float* __restrict__ phase,
    const float* __restrict__ outA,       // (5,)
    const float* __restrict__ outB,       // (5,)
    const float* __restrict__ nw,         // (5,)
    const float* __restrict__ fc1,        // (2,5)
    const float* __restrict__ hp,         // (2,5)
    float*       __restrict__ out,        // (B,34,10)
    int B)
{
    __shared__ float  s_W [T_LEN * WSTRIDE];       // E -> folded F (4.9 KB)
    __shared__ unsigned char s_c[SPB * CSTRIDE];   // digits (2.2 KB)
    __shared__ __align__(16) float s_u0[SPB * USTRIDE];  // dA -> u0, stride 35 conflict-free
    __shared__ __align__(16) float s_u1[SPB * USTRIDE];  // u1
    __shared__ float4 s_xc[10];                    // (x0,x1,Vt,0)
    __shared__ float2 s_tt[10];                    // (x0,x1)
    __shared__ float4 s_xp[T_LEN];                 // (p0,p1,p2,0)
    __shared__ float  s_r [T_LEN];
    __shared__ float  s_dinv[T_LEN];
    __shared__ float  s_sc[40];                    // cB[0..4], hp[5..14], wf[15..24], wh[25..34]

    // build-time overlays on s_u0 (dead until matvec writes)
    float4* s_mt = reinterpret_cast<float4*>(s_u0);          // [34]
    float4* s_pt = reinterpret_cast<float4*>(s_u0) + T_LEN;  // [34]

    const int  tid       = threadIdx.x;
    const long base_tok  = (long)blockIdx.x * NTOK;
    const long total_tok = (long)B * T_LEN;

    // ---- P1: idx -> digits; parameter tables ----
    #pragma unroll
    for (int r = 0; r < 17; ++r) {
        int li = tid + r * BT;                   // 0..2175
        int  yy = li / T_LEN;
        int  ss = li - yy * T_LEN;
        long g  = base_tok + li;
        int  v  = (g < total_tok) ? idx[g] : 0;
        s_c[yy * CSTRIDE + ss] = (unsigned char)v;
    }
    if (tid < 40) {                              // scalar params
        int i = tid;
        float v = 0.f;
        if (i < 5)       v = outB[i];
        else if (i < 15) v = hp[i - 5];
        else if (i < 25) v = nw[(i - 15) % 5] * fc1[i - 15];
        else if (i < 35) v = nw[(i - 25) % 5] * hp[i - 25];
        s_sc[i] = v;
    }
    if (tid >= 64 && tid < 64 + T_LEN) {         // warps 2-3: positions
        const int t = tid - 64;
        const int f = c_flat[t];
        float p0, p1, p2;
        if (f < 10) {
            float a = 0.6283185307179586f * (float)f;
            p0 = 3.5f * __cosf(a);
            p1 = 3.5f * __sinf(a);
            p2 = 0.15f * (float)f;
        } else if (f == 10) {
            p0 = z_hi[0]; p1 = z_hi[1]; p2 = z_hi[2];
        } else if (f == 12) {
            p0 = specialEq[0]; p1 = specialEq[1]; p2 = specialEq[2];
        } else {
            p0 = p1 = p2 = 0.0f;
        }
        float pp = p0*p0 + p1*p1 + p2*p2;
        s_xp[t] = make_float4(p0, p1, p2, 0.f);

        float amp = tokA[0];
        s_r[t] = rsqrtf(fmaf(0.2f, fmaf(amp, amp, pp), 1e-5f));

        float pt0 = p0 * nw[2], pt1 = p1 * nw[3], pt2 = p2 * nw[4];
        s_pt[t] = make_float4(pt0, pt1, pt2, 0.f);

        float q0 = qW[0]*pt0 + qW[1]*pt1 + qW[2]*pt2;
        float q1 = qW[3]*pt0 + qW[4]*pt1 + qW[5]*pt2;
        float q2 = qW[6]*pt0 + qW[7]*pt1 + qW[8]*pt2;
        float q3 = qW[9]*pt0 + qW[10]*pt1 + qW[11]*pt2;
        float cp = __cosf(phase[0]);
        float sp = __sinf(phase[0]);
        float r0  = q0*cp - q1*sp;
        float r1v = q0*sp + q1*cp;
        float r2v = q2*cp - q3*sp;
        float r3  = q2*sp + q3*cp;
        const float LG = 0.5f * 1.4426950408889634f;
        s_mt[t] = make_float4(
            LG*(r0*qW[0] + r1v*qW[3] + r2v*qW[6] + r3*qW[9]),
            LG*(r0*qW[1] + r1v*qW[4] + r2v*qW[7] + r3*qW[10]),
            LG*(r0*qW[2] + r1v*qW[5] + r2v*qW[8] + r3*qW[11]), 0.f);
    }
    if (tid >= 48 && tid < 58) {                 // warp 1: digit table
        const int c = tid - 48;
        float ang = tokStart[0] + (float)c * tokStride[0];
        float amp = tokA[0];
        float x0 = amp * __cosf(ang);
        float x1 = amp * __sinf(ang);
        float w0s = hp[0]*outA[0] + hp[1]*outA[1] + hp[2]*outA[2] + hp[3]*outA[3] + hp[4]*outA[4];
        float w1s = hp[5]*outA[0] + hp[6]*outA[1] + hp[7]*outA[2] + hp[8]*outA[3] + hp[9]*outA[4];
        float vt  = x0 * nw[0] * w0s + x1 * nw[1] * w1s;
        s_xc[c] = make_float4(x0, x1, vt, 0.f);
        s_tt[c] = make_float2(x0, x1);
    }
    __syncthreads();

    // ---- P2: E[t][s] = exp2(r_t r_s g(t,s)) ----
    #pragma unroll 1
    for (int li = tid; li < T_LEN * T_LEN; li += BT) {
        int t = li / T_LEN;
        int s = li - t * T_LEN;
        if (s <= t) {
            float4 m = s_mt[t];
            float4 p = s_pt[s];
            float g  = fmaf(m.x, p.x, fmaf(m.y, p.y, m.z * p.z));
            s_W[t * WSTRIDE + s] = ex2f((s_r[t] * s_r[s]) * g);
        }
    }
    __syncthreads();

    // ---- P3a: row denominators ----
    if (tid < T_LEN) {
        const float* wr = s_W + tid * WSTRIDE;
        float d0 = 0.f, d1 = 0.f;
        const int nf = ((tid + 1) >> 2) << 2;
        for (int s = 0; s < nf; s += 4) {
            float4 w4 = *(const float4*)(wr + s);
            d0 += w4.x + w4.z;
            d1 += w4.y + w4.w;
        }
        for (int s = nf; s <= tid; ++s) d0 += wr[s];
        s_dinv[tid] = rcpf(d0 + d1);
    }
    __syncthreads();

    // ---- P3b: fold F = E * dinv[t] * r[s] ----
    #pragma unroll 1
    for (int li = tid; li < T_LEN * T_LEN; li += BT) {
        int t = li / T_LEN;
        int s = li - t * T_LEN;
        if (s <= t) s_W[t * WSTRIDE + s] *= s_dinv[t] * s_r[s];
    }
    __syncthreads();

    // ---- P4: triangular matvec, thread-per-sequence, dA -> s_u0 ----
    {
        const int role = tid >> 6;
        const int y    = tid & 63;
        const unsigned char* __restrict__ crow = s_c + y * CSTRIDE;
        float* __restrict__ du = s_u0 + y * USTRIDE;
        if (role == 0) matvec_seq<0, 24>(crow, s_W, s_xc, du);
        else           matvec_seq<24, T_LEN>(crow, s_W, s_xc, du);
    }
    __syncthreads();

    const float* s_cB = s_sc;
    const float* s_hp = s_sc + 5;
    const float* s_wf = s_sc + 15;
    const float* s_wh = s_sc + 25;

    // ---- P5: epilogue per token, in-place: dA -> (u0,u1) (conflict-free) ----
    #pragma unroll 1
    for (int r = 0; r < 17; ++r) {
        int it = tid + r * BT;                   // 0..2175
        const int t = it >> 6;                   // warp-uniform
        const int y = it & 63;
        const int ui = y * USTRIDE + t;
        const float dA = s_u0[ui];
        const int c = (int)s_c[y * CSTRIDE + t];

        const float4 xc = s_xc[c];
        const float4 xp = s_xp[t];
        float X0 = fmaf(dA, s_cB[0], xc.x);
        float X1 = fmaf(dA, s_cB[1], xc.y);
        float X2 = fmaf(dA, s_cB[2], xp.x);
        float X3 = fmaf(dA, s_cB[3], xp.y);
        float X4 = fmaf(dA, s_cB[4], xp.z);

        float ss1 = fmaf(X0,X0, fmaf(X1,X1, fmaf(X2,X2, fmaf(X3,X3, X4*X4))));
        float r1  = rsqrtf(fmaf(0.2f, ss1, 1e-5f));
        float z0 = r1 * (X0*s_wf[0] + X1*s_wf[1] + X2*s_wf[2] + X3*s_wf[3] + X4*s_wf[4]);
        float z1 = r1 * (X0*s_wf[5] + X1*s_wf[6] + X2*s_wf[7] + X3*s_wf[8] + X4*s_wf[9]);
        float g0 = gelu_fast(z0);
        float g1 = gelu_fast(z1);
        float Y0 = X0 + g0*s_hp[0] + g1*s_hp[5];
        float Y1 = X1 + g0*s_hp[1] + g1*s_hp[6];
        float Y2 = X2 + g0*s_hp[2] + g1*s_hp[7];
        float Y3 = X3 + g0*s_hp[3] + g1*s_hp[8];
        float Y4 = X4 + g0*s_hp[4] + g1*s_hp[9];

        float ss2 = fmaf(Y0,Y0, fmaf(Y1,Y1, fmaf(Y2,Y2, fmaf(Y3,Y3, Y4*Y4))));
        float r2  = rsqrtf(fmaf(0.2f, ss2, 1e-5f));
        float u0 = r2 * (Y0*s_wh[0] + Y1*s_wh[1] + Y2*s_wh[2] + Y3*s_wh[3] + Y4*s_wh[4]);
        float u1 = r2 * (Y0*s_wh[5] + Y1*s_wh[6] + Y2*s_wh[7] + Y3*s_wh[8] + Y4*s_wh[9]);

        s_u0[ui] = u0;
        s_u1[ui] = u1;
    }
    __syncthreads();

    // ---- P6: coalesced float4 output (R15 pattern; li = tq + tq/34) ----
    const long base_f  = base_tok * 10;
    const long total_f = total_tok * 10;
    float* __restrict__ ob = out + base_f;
    const int nf4 = (NTOK * 10) / 4;             // 5440

    for (int f4 = tid; f4 < nf4; f4 += BT) {
        const int el = f4 * 4;
        if (base_f + el + 4 <= total_f) {
            int tq = el / 10;
            int d  = el - tq * 10;
            int li = tq + tq / T_LEN;            // y*35 + t
            float u0 = s_u0[li];
            float u1 = s_u1[li];
            float vv[4];
            #pragma unroll
            for (int k2 = 0; k2 < 4; ++k2) {
                float2 w = s_tt[d];
                vv[k2] = fmaf(u1, w.y, u0 * w.x);
                if (++d == 10) {
                    d = 0; ++tq;
                    li = tq + tq / T_LEN;
                    u0 = s_u0[li]; u1 = s_u1[li];
                }
            }
            reinterpret_cast<float4*>(ob)[f4] = make_float4(vv[0], vv[1], vv[2], vv[3]);
        }
    }
}

extern "C" void kernel_launch(void* const* d_in, const int* in_sizes, int n_in,
                              void* d_out, int out_size)
{
    const int B = in_sizes[0] / T_LEN;
    const int grid = (B + SPB - 1) / SPB;
    micro_fused17<<<grid, BT>>>(
        (const int*)d_in[0],
        (const float*)d_in[1],
        (const float*)d_in[2],
        (const float*)d_in[3],
        (const float*)d_in[4],
        (const float*)d_in[5],
        (const float*)d_in[6],
        (const float*)d_in[7],
        (const float*)d_in[8],
        (const float*)d_in[9],
        (const float*)d_in[10],
        (const float*)d_in[11],
        (const float*)d_in[12],
        (float*)d_out, B);
}